// round 3
// baseline (speedup 1.0000x reference)
#include <cuda_runtime.h>

// ----------------------------------------------------------------------------
// FBP pipeline (2 kernels):
//   K1: filter  — circular conv of the 16 BASE frames with the exact
//       closed-form ramp kernel (h[0]=1/4, h odd = -1/(16384 sin^2(pi n/128)),
//       h even = 0), scaled by pi/128.  (filter ∘ lerp = lerp ∘ filter)
//   K2: backproject — 2 slices per block; lerp 16 frames -> 128 angle rows in
//       smem (guard-padded, 192 KB total); conflict-free mapping: lane = y
//       (consecutive), so LDS addresses are monotone with span < 32 -> no
//       bank conflicts at any angle. Index math shared across both slices.
// ----------------------------------------------------------------------------

#define MPIF 3.14159265358979323846f

__device__ float g_Fbase[16 * 1024 * 128];       // filtered base frames, 8 MB

// --------------------------- K1: filter -------------------------------------
// One warp per row (t,c,h): F[j] = sum_k p[k] * h[(j-k) mod 128]
__global__ __launch_bounds__(256) void k_filter(const float* __restrict__ feat) {
    __shared__ float hk[256];                    // hker duplicated: hk[i]=h[i&127]
    int tid = threadIdx.x;
    {
        int n = tid & 127;
        float h;
        if (n == 0) h = 0.25f;
        else if (n & 1) {
            float sv = sinpif((float)n * (1.0f / 128.0f));
            h = -1.0f / (16384.0f * sv * sv);
        } else h = 0.0f;
        hk[tid] = h * (MPIF / 128.0f);           // fold pi/A scale into filter
    }
    __syncthreads();

    int lane = tid & 31;
    int wid  = tid >> 5;
    int r = blockIdx.x * 8 + wid;                // row 0..16383
    const float* row = feat + (size_t)r * 128;

    float rv[4];
    rv[0] = row[lane];      rv[1] = row[lane + 32];
    rv[2] = row[lane + 64]; rv[3] = row[lane + 96];
    float a0 = 0.f, a1 = 0.f, a2 = 0.f, a3 = 0.f;

#pragma unroll
    for (int kb = 0; kb < 4; kb++) {
        float rsel = rv[kb];
#pragma unroll
        for (int kk = 0; kk < 32; kk++) {
            float x = __shfl_sync(0xffffffffu, rsel, kk);
            int base = lane + 128 - (kb * 32 + kk);   // in [1,255]
            a0 += x * hk[base];
            a1 += x * hk[base + 32];
            a2 += x * hk[base + 64];
            a3 += x * hk[base + 96];
        }
    }
    float* o = g_Fbase + (size_t)r * 128;
    o[lane] = a0; o[lane + 32] = a1; o[lane + 64] = a2; o[lane + 96] = a3;
}

// ------------------------ K2: backprojection --------------------------------
// grid = 512 blocks (2 slices each); 512 threads; dyn smem = 2 x FA[128][192].
// Thread (warp w, lane l): pixels x = w + 16*i (i<8), y = 32*j + l (j<4),
// both slices. Within one LDS the lane addresses step by sin(theta) in [0,1]
// -> span < 32 consecutive columns -> conflict-free.
extern __shared__ float s_FA[];

static constexpr int FA_STRIDE = 192;              // padded row (floats)
static constexpr int FA_SLICE  = 128 * FA_STRIDE;  // floats per slice (24576)

__global__ __launch_bounds__(512, 1) void k_bp(float* __restrict__ out) {
    __shared__ float sc[128], ss[128];

    int tid = threadIdx.x;
    int s0  = blockIdx.x * 2;                    // slices s0, s0+1

    if (tid < 128) {
        float t = (float)tid * (1.0f / 128.0f);
        sc[tid] = cospif(t);
        ss[tid] = sinpif(t);
    }

    // zero guard bands: 2 slices x 128 angles x (32 left + 32 right)
    for (int g = tid; g < 2 * 8192; g += 512) {
        int sl = g >> 13;
        int gg = g & 8191;
        int a = gg >> 6;
        int q = gg & 63;
        int col = (q < 32) ? q : (128 + q);      // [0,32) and [160,192)
        s_FA[sl * FA_SLICE + a * FA_STRIDE + col] = 0.f;
    }

    // interior: lerp 16 filtered base frames -> 128 angle rows, both slices
    for (int e = tid; e < 2 * 16384; e += 512) {
        int sl = e >> 14;
        int ee = e & 16383;
        int a = ee >> 7, w = ee & 127;
        int t0 = a >> 3;
        float v = (float)(a & 7) * 0.125f;
        int s = s0 + sl;
        float f0 = g_Fbase[(size_t)(t0 * 1024 + s) * 128 + w];
        float f1 = g_Fbase[(size_t)(((t0 + 1) & 15) * 1024 + s) * 128 + w];
        s_FA[sl * FA_SLICE + a * FA_STRIDE + 32 + w] = fmaf(v, f1 - f0, f0);
    }
    __syncthreads();

    int w = tid >> 5;                            // warp 0..15
    int l = tid & 31;                            // lane = y within block
    float xb = (float)w - 63.5f;                 // x = w + 16*i

    float acc0[32], acc1[32];                    // [i*4 + j], per slice
#pragma unroll
    for (int i = 0; i < 32; i++) { acc0[i] = 0.f; acc1[i] = 0.f; }

    for (int a = 0; a < 128; a++) {
        float c  = sc[a];
        float sn = ss[a];
        // +63.5 detector center, +32 guard offset, + lane*sin
        float lsn = fmaf((float)l, sn, 95.5f);
        const float* r0 = s_FA + a * FA_STRIDE;
        const float* r1 = r0 + FA_SLICE;
#pragma unroll
        for (int i = 0; i < 8; i++) {
            float xc = fmaf(xb + (float)(16 * i), c, lsn);
#pragma unroll
            for (int j = 0; j < 4; j++) {
                float u  = fmaf((float)(32 * j) - 63.5f, sn, xc);
                float t  = u + 8388607.5f;                 // 2^23-0.5: RN->floor
                int   it = __float_as_int(t) - 0x4B000000; // floor(u) as int
                float fl = t - 8388608.0f;                 // floor(u), exact
                float fr = u - fl;                         // frac, exact
                float om = 1.0f - fr;
                float g0a = r0[it], g1a = r0[it + 1];
                float g0b = r1[it], g1b = r1[it + 1];
                int k = i * 4 + j;
                acc0[k] = fmaf(g0a, om, fmaf(g1a, fr, acc0[k]));
                acc1[k] = fmaf(g0b, om, fmaf(g1b, fr, acc1[k]));
            }
        }
    }

    // out[s, x, y]: x = w + 16*i, y = 32*j + l; lane-consecutive -> coalesced
    float* ob = out + (size_t)s0 * 16384 + l;
#pragma unroll
    for (int i = 0; i < 8; i++) {
#pragma unroll
        for (int j = 0; j < 4; j++) {
            int k = i * 4 + j;
            int off = (w + 16 * i) * 128 + 32 * j;
            ob[off] = acc0[k];
            ob[16384 + off] = acc1[k];
        }
    }
}

// ----------------------------------------------------------------------------
extern "C" void kernel_launch(void* const* d_in, const int* in_sizes, int n_in,
                              void* d_out, int out_size) {
    (void)in_sizes; (void)n_in; (void)out_size;
    const float* feat = (const float*)d_in[0];
    float* out = (float*)d_out;

    int smem_bytes = 2 * FA_SLICE * (int)sizeof(float);   // 196608
    cudaFuncSetAttribute(k_bp, cudaFuncAttributeMaxDynamicSharedMemorySize,
                         smem_bytes);

    k_filter<<<2048, 256>>>(feat);
    k_bp<<<512, 512, smem_bytes>>>(out);
}

// round 4
// speedup vs baseline: 1.6243x; 1.6243x over previous
#include <cuda_runtime.h>

// ----------------------------------------------------------------------------
// FBP pipeline (2 kernels):
//   K1: filter  — circular conv of the 16 BASE frames with the exact
//       closed-form ramp kernel (h[0]=1/4, h odd = -1/(16384 sin^2(pi n/128)),
//       h even = 0), scaled by pi/128.  (filter ∘ lerp = lerp ∘ filter)
//   K2: backproject — 2 slices per block; lerp 16 frames -> 128 angle rows in
//       smem (guard-padded, 192 KB total); conflict-free mapping: lane = y
//       (consecutive), so LDS addresses are monotone with span < 32 -> no
//       bank conflicts at any angle. Index math shared across both slices.
// ----------------------------------------------------------------------------

#define MPIF 3.14159265358979323846f

__device__ float g_Fbase[16 * 1024 * 128];       // filtered base frames, 8 MB

// --------------------------- K1: filter -------------------------------------
// One warp per row (t,c,h): F[j] = sum_k p[k] * h[(j-k) mod 128]
__global__ __launch_bounds__(256) void k_filter(const float* __restrict__ feat) {
    __shared__ float hk[256];                    // hker duplicated: hk[i]=h[i&127]
    int tid = threadIdx.x;
    {
        int n = tid & 127;
        float h;
        if (n == 0) h = 0.25f;
        else if (n & 1) {
            float sv = sinpif((float)n * (1.0f / 128.0f));
            h = -1.0f / (16384.0f * sv * sv);
        } else h = 0.0f;
        hk[tid] = h * (MPIF / 128.0f);           // fold pi/A scale into filter
    }
    __syncthreads();

    int lane = tid & 31;
    int wid  = tid >> 5;
    int r = blockIdx.x * 8 + wid;                // row 0..16383
    const float* row = feat + (size_t)r * 128;

    float rv[4];
    rv[0] = row[lane];      rv[1] = row[lane + 32];
    rv[2] = row[lane + 64]; rv[3] = row[lane + 96];
    float a0 = 0.f, a1 = 0.f, a2 = 0.f, a3 = 0.f;

#pragma unroll
    for (int kb = 0; kb < 4; kb++) {
        float rsel = rv[kb];
#pragma unroll
        for (int kk = 0; kk < 32; kk++) {
            float x = __shfl_sync(0xffffffffu, rsel, kk);
            int base = lane + 128 - (kb * 32 + kk);   // in [1,255]
            a0 += x * hk[base];
            a1 += x * hk[base + 32];
            a2 += x * hk[base + 64];
            a3 += x * hk[base + 96];
        }
    }
    float* o = g_Fbase + (size_t)r * 128;
    o[lane] = a0; o[lane + 32] = a1; o[lane + 64] = a2; o[lane + 96] = a3;
}

// ------------------------ K2: backprojection --------------------------------
// grid = 512 blocks (2 slices each); 512 threads; dyn smem = 2 x FA[128][192].
// Thread (warp w, lane l): pixels x = w + 16*i (i<8), y = 32*j + l (j<4),
// both slices. Within one LDS the lane addresses step by sin(theta) in [0,1]
// -> span < 32 consecutive columns -> conflict-free.
extern __shared__ float s_FA[];

static constexpr int FA_STRIDE = 192;              // padded row (floats)
static constexpr int FA_SLICE  = 128 * FA_STRIDE;  // floats per slice (24576)

__global__ __launch_bounds__(512, 1) void k_bp(float* __restrict__ out) {
    __shared__ float sc[128], ss[128];

    int tid = threadIdx.x;
    int s0  = blockIdx.x * 2;                    // slices s0, s0+1

    if (tid < 128) {
        float t = (float)tid * (1.0f / 128.0f);
        sc[tid] = cospif(t);
        ss[tid] = sinpif(t);
    }

    // zero guard bands: 2 slices x 128 angles x (32 left + 32 right)
    for (int g = tid; g < 2 * 8192; g += 512) {
        int sl = g >> 13;
        int gg = g & 8191;
        int a = gg >> 6;
        int q = gg & 63;
        int col = (q < 32) ? q : (128 + q);      // [0,32) and [160,192)
        s_FA[sl * FA_SLICE + a * FA_STRIDE + col] = 0.f;
    }

    // interior: lerp 16 filtered base frames -> 128 angle rows, both slices
    for (int e = tid; e < 2 * 16384; e += 512) {
        int sl = e >> 14;
        int ee = e & 16383;
        int a = ee >> 7, w = ee & 127;
        int t0 = a >> 3;
        float v = (float)(a & 7) * 0.125f;
        int s = s0 + sl;
        float f0 = g_Fbase[(size_t)(t0 * 1024 + s) * 128 + w];
        float f1 = g_Fbase[(size_t)(((t0 + 1) & 15) * 1024 + s) * 128 + w];
        s_FA[sl * FA_SLICE + a * FA_STRIDE + 32 + w] = fmaf(v, f1 - f0, f0);
    }
    __syncthreads();

    int w = tid >> 5;                            // warp 0..15
    int l = tid & 31;                            // lane = y within block
    float xb = (float)w - 63.5f;                 // x = w + 16*i

    float acc0[32], acc1[32];                    // [i*4 + j], per slice
#pragma unroll
    for (int i = 0; i < 32; i++) { acc0[i] = 0.f; acc1[i] = 0.f; }

    for (int a = 0; a < 128; a++) {
        float c  = sc[a];
        float sn = ss[a];
        // +63.5 detector center, +32 guard offset, + lane*sin
        float lsn = fmaf((float)l, sn, 95.5f);
        const float* r0 = s_FA + a * FA_STRIDE;
        const float* r1 = r0 + FA_SLICE;
#pragma unroll
        for (int i = 0; i < 8; i++) {
            float xc = fmaf(xb + (float)(16 * i), c, lsn);
#pragma unroll
            for (int j = 0; j < 4; j++) {
                float u  = fmaf((float)(32 * j) - 63.5f, sn, xc);
                float t  = u + 8388607.5f;                 // 2^23-0.5: RN->floor
                int   it = __float_as_int(t) - 0x4B000000; // floor(u) as int
                float fl = t - 8388608.0f;                 // floor(u), exact
                float fr = u - fl;                         // frac, exact
                float om = 1.0f - fr;
                float g0a = r0[it], g1a = r0[it + 1];
                float g0b = r1[it], g1b = r1[it + 1];
                int k = i * 4 + j;
                acc0[k] = fmaf(g0a, om, fmaf(g1a, fr, acc0[k]));
                acc1[k] = fmaf(g0b, om, fmaf(g1b, fr, acc1[k]));
            }
        }
    }

    // out[s, x, y]: x = w + 16*i, y = 32*j + l; lane-consecutive -> coalesced
    float* ob = out + (size_t)s0 * 16384 + l;
#pragma unroll
    for (int i = 0; i < 8; i++) {
#pragma unroll
        for (int j = 0; j < 4; j++) {
            int k = i * 4 + j;
            int off = (w + 16 * i) * 128 + 32 * j;
            ob[off] = acc0[k];
            ob[16384 + off] = acc1[k];
        }
    }
}

// ----------------------------------------------------------------------------
extern "C" void kernel_launch(void* const* d_in, const int* in_sizes, int n_in,
                              void* d_out, int out_size) {
    (void)in_sizes; (void)n_in; (void)out_size;
    const float* feat = (const float*)d_in[0];
    float* out = (float*)d_out;

    int smem_bytes = 2 * FA_SLICE * (int)sizeof(float);   // 196608
    cudaFuncSetAttribute(k_bp, cudaFuncAttributeMaxDynamicSharedMemorySize,
                         smem_bytes);

    k_filter<<<2048, 256>>>(feat);
    k_bp<<<512, 512, smem_bytes>>>(out);
}